// round 2
// baseline (speedup 1.0000x reference)
#include <cuda_runtime.h>
#include <cstdint>

#define BATCH 2
#define DIM   128
#define HS    62
#define HX    248
#define PS_S  (HS*HS)   // 3844
#define PS_X  (HX*HX)   // 61504
#define NWIN  100       // 10x10 windows

// ---------------- scratch (static device buffers; no allocation allowed) ----
__device__ float g_xp  [BATCH*DIM*PS_X];        // x + pos-conv
__device__ float g_spp [BATCH*DIM*PS_S];        // sp + pos-conv
__device__ float g_tkv [BATCH*2*DIM*PS_X];      // conv1(kv) pre-dw
__device__ float g_kv  [BATCH*2*DIM*PS_X];      // kv after depthwise
__device__ float g_tq  [BATCH*DIM*PS_S];        // conv1(q) pre-dw
__device__ float g_q   [BATCH*DIM*PS_S];        // q after depthwise
__device__ float g_win [BATCH*NWIN*DIM*64];     // attention output windows
__device__ float g_acc [BATCH*DIM*PS_S];        // reverse output
__device__ float g_wq_t  [DIM*DIM];             // transposed weights (K-major)
__device__ float g_wkv_t [DIM*2*DIM];
__device__ float g_wout_t[DIM*DIM];

// ---------------- weight transpose: wt[c*O+o] = w[o*C+c] ---------------------
__global__ void transpose_kernel(const float* __restrict__ w, float* __restrict__ wt,
                                 int O, int C) {
    int idx = blockIdx.x * 256 + threadIdx.x;
    if (idx >= O * C) return;
    int o = idx / C, c = idx % C;
    wt[c * O + o] = w[idx];
}

// ---------------- depthwise 3x3 (optionally residual + bias) ----------------
template<bool RES, bool BIAS>
__global__ void dw3_kernel(const float* __restrict__ in, float* __restrict__ out,
                           const float* __restrict__ w, const float* __restrict__ bias,
                           int H, int W, int cmod) {
    int plane = blockIdx.y;
    int p = blockIdx.x * 256 + threadIdx.x;
    int HW = H * W;
    if (p >= HW) return;
    int y = p / W, x = p % W;
    int c = plane % cmod;
    const float* ip = in + (size_t)plane * HW;
    float acc = BIAS ? bias[c] : 0.0f;
    const float* wc = w + c * 9;
#pragma unroll
    for (int ky = 0; ky < 3; ky++) {
        int yy = y + ky - 1;
        if ((unsigned)yy >= (unsigned)H) continue;
#pragma unroll
        for (int kx = 0; kx < 3; kx++) {
            int xx = x + kx - 1;
            if ((unsigned)xx >= (unsigned)W) continue;
            acc += ip[yy * W + xx] * wc[ky * 3 + kx];
        }
    }
    out[(size_t)plane * HW + p] = RES ? (ip[p] + acc) : acc;
}

// ---------------- conv1 as GEMM: out[o,p] = sum_c Wt[c,o] * in[c,p] ---------
// C = 128 fixed. Block computes 128 (O) x 128 (P), 256 threads, 8x8 micro-tile.
__global__ __launch_bounds__(256)
void conv1_gemm(const float* __restrict__ Wt, const float* __restrict__ in,
                float* __restrict__ out, int O, int P) {
    __shared__ float Ws[8][128];
    __shared__ float Xs[8][132];

    const float* inb = in + (size_t)blockIdx.z * 128 * P;
    float* outb = out + (size_t)blockIdx.z * O * P;

    int p0 = blockIdx.x * 128;
    int o0 = blockIdx.y * 128;
    int tid = threadIdx.x;
    int ty = tid / 16, tx = tid % 16;   // ty: O groups of 8, tx: P groups of 8

    float acc[8][8];
#pragma unroll
    for (int i = 0; i < 8; i++)
#pragma unroll
        for (int j = 0; j < 8; j++) acc[i][j] = 0.0f;

    for (int k0 = 0; k0 < 128; k0 += 8) {
        // load W tile (coalesced: Wt is K-major)
#pragma unroll
        for (int l = 0; l < 4; l++) {
            int e = tid + l * 256;          // 1024 elems
            int k = e >> 7, o = e & 127;
            Ws[k][o] = Wt[(k0 + k) * O + o0 + o];
        }
        // load X tile
#pragma unroll
        for (int l = 0; l < 4; l++) {
            int e = tid + l * 256;
            int k = e >> 7, p = e & 127;
            int gp = p0 + p;
            Xs[k][p] = (gp < P) ? inb[(size_t)(k0 + k) * P + gp] : 0.0f;
        }
        __syncthreads();
#pragma unroll
        for (int kk = 0; kk < 8; kk++) {
            float4 a0 = *(const float4*)&Ws[kk][ty * 8];
            float4 a1 = *(const float4*)&Ws[kk][ty * 8 + 4];
            float4 b0 = *(const float4*)&Xs[kk][tx * 8];
            float4 b1 = *(const float4*)&Xs[kk][tx * 8 + 4];
            float av[8] = {a0.x, a0.y, a0.z, a0.w, a1.x, a1.y, a1.z, a1.w};
            float bv[8] = {b0.x, b0.y, b0.z, b0.w, b1.x, b1.y, b1.z, b1.w};
#pragma unroll
            for (int i = 0; i < 8; i++)
#pragma unroll
                for (int j = 0; j < 8; j++) acc[i][j] += av[i] * bv[j];
        }
        __syncthreads();
    }

#pragma unroll
    for (int i = 0; i < 8; i++) {
        int o = o0 + ty * 8 + i;            // O is a multiple of 128 -> in bounds
        float* row = outb + (size_t)o * P;
#pragma unroll
        for (int j = 0; j < 8; j++) {
            int gp = p0 + tx * 8 + j;
            if (gp < P) row[gp] = acc[i][j];
        }
    }
}

// ---------------- windowed attention (flash-style streaming softmax) --------
// block = (bn in [0,200), head in [0,4)), 256 threads = 8 warps.
// Each warp owns 8 q-rows; each lane owns output channel c = lane.
__global__ __launch_bounds__(256)
void attn_kernel() {
    __shared__ float qs[64][33];
    __shared__ float ks[64][33];
    __shared__ float vs[64][33];
    __shared__ float ps[64][64];

    int bn = blockIdx.x;
    int h  = blockIdx.y;
    int b = bn / NWIN, n = bn % NWIN;
    int wh = n / 10, ww = n % 10;
    int tid = threadIdx.x, lane = tid & 31, warp = tid >> 5;

    int y0q = 6 * wh, x0q = 6 * ww;
    int y0k = 24 * wh, x0k = 24 * ww;

    const float scale = 0.17677669529663687f; // 1/sqrt(32)

    // load q window (fold in scale)
    for (int e = tid; e < 2048; e += 256) {
        int c = e >> 6, i = e & 63;
        int dy = i >> 3, dx = i & 7;
        qs[i][c] = g_q[((size_t)(b * DIM + h * 32 + c) * HS + y0q + dy) * HS + x0q + dx] * scale;
    }

    float acc[8], m[8], l[8];
#pragma unroll
    for (int r = 0; r < 8; r++) { acc[r] = 0.0f; m[r] = -1e30f; l[r] = 0.0f; }
    __syncthreads();

    for (int c0 = 0; c0 < 1024; c0 += 64) {
        // load k/v chunk: 64 kv-positions x 32 channels
        for (int e = tid; e < 2048; e += 256) {
            int ch = e >> 6, j = e & 63;
            int kj = c0 + j;
            int ky = y0k + (kj >> 5), kx = x0k + (kj & 31);
            ks[j][ch] = g_kv[((size_t)(b * 2 * DIM + h * 32 + ch) * HX + ky) * HX + kx];
            vs[j][ch] = g_kv[((size_t)(b * 2 * DIM + DIM + h * 32 + ch) * HX + ky) * HX + kx];
        }
        __syncthreads();

#pragma unroll
        for (int r = 0; r < 8; r++) {
            int i = warp * 8 + r;
            float s0 = 0.0f, s1 = 0.0f;
#pragma unroll
            for (int c = 0; c < 32; c++) {
                float qv = qs[i][c];
                s0 += qv * ks[lane][c];
                s1 += qv * ks[lane + 32][c];
            }
            float mx = fmaxf(s0, s1);
#pragma unroll
            for (int off = 16; off; off >>= 1)
                mx = fmaxf(mx, __shfl_xor_sync(0xFFFFFFFFu, mx, off));
            float mnew = fmaxf(m[r], mx);
            float corr = __expf(m[r] - mnew);
            float p0 = __expf(s0 - mnew);
            float p1 = __expf(s1 - mnew);
            float psum = p0 + p1;
#pragma unroll
            for (int off = 16; off; off >>= 1)
                psum += __shfl_xor_sync(0xFFFFFFFFu, psum, off);
            m[r] = mnew;
            l[r] = l[r] * corr + psum;
            acc[r] *= corr;
            ps[i][lane] = p0;
            ps[i][lane + 32] = p1;
        }
        __syncwarp();

        // acc[r][lane] += sum_j p[i][j] * v[j][lane]
#pragma unroll 4
        for (int j = 0; j < 64; j++) {
            float vv = vs[j][lane];
#pragma unroll
            for (int r = 0; r < 8; r++)
                acc[r] += ps[warp * 8 + r][j] * vv;
        }
        __syncthreads();
    }

#pragma unroll
    for (int r = 0; r < 8; r++) {
        int i = warp * 8 + r;
        g_win[((size_t)bn * DIM + h * 32 + lane) * 64 + i] = acc[r] / l[r];
    }
}

// ---------------- reverse (overlap-add with count normalization) ------------
__global__ void reverse_kernel() {
    int idx = blockIdx.x * 256 + threadIdx.x;
    if (idx >= BATCH * DIM * PS_S) return;
    int x = idx % HS;
    int y = (idx / HS) % HS;
    int c = (idx / PS_S) % DIM;
    int b = idx / (PS_S * DIM);

    int wlo = max(0, (y - 2) / 6), whi = min(9, y / 6);
    int vlo = max(0, (x - 2) / 6), vhi = min(9, x / 6);
    float s = 0.0f;
    for (int wh = wlo; wh <= whi; wh++) {
        int dy = y - 6 * wh;
        for (int ww = vlo; ww <= vhi; ww++) {
            int dx = x - 6 * ww;
            int n = wh * 10 + ww;
            s += g_win[((size_t)(b * NWIN + n) * DIM + c) * 64 + dy * 8 + dx];
        }
    }
    int cnt = (whi - wlo + 1) * (vhi - vlo + 1);
    g_acc[idx] = s / (float)cnt;
}

// ---------------- launch --------------------------------------------------
extern "C" void kernel_launch(void* const* d_in, const int* in_sizes, int n_in,
                              void* d_out, int out_size) {
    const float* x     = (const float*)d_in[0];
    const float* sp    = (const float*)d_in[1];
    const float* w_pos = (const float*)d_in[2];
    const float* b_pos = (const float*)d_in[3];
    const float* w_q   = (const float*)d_in[4];
    const float* w_qdw = (const float*)d_in[5];
    const float* w_kv  = (const float*)d_in[6];
    const float* w_kvdw= (const float*)d_in[7];
    const float* w_out = (const float*)d_in[8];
    float* out = (float*)d_out;

    float *xp, *spp, *tkv, *kv, *tq, *q, *acc, *wq_t, *wkv_t, *wout_t;
    cudaGetSymbolAddress((void**)&xp,    g_xp);
    cudaGetSymbolAddress((void**)&spp,   g_spp);
    cudaGetSymbolAddress((void**)&tkv,   g_tkv);
    cudaGetSymbolAddress((void**)&kv,    g_kv);
    cudaGetSymbolAddress((void**)&tq,    g_tq);
    cudaGetSymbolAddress((void**)&q,     g_q);
    cudaGetSymbolAddress((void**)&acc,   g_acc);
    cudaGetSymbolAddress((void**)&wq_t,  g_wq_t);
    cudaGetSymbolAddress((void**)&wkv_t, g_wkv_t);
    cudaGetSymbolAddress((void**)&wout_t,g_wout_t);

    // weight transposes (K-major for coalesced GEMM loads)
    transpose_kernel<<<(DIM*DIM + 255)/256, 256>>>(w_q,   wq_t,   DIM,   DIM);
    transpose_kernel<<<(2*DIM*DIM + 255)/256, 256>>>(w_kv, wkv_t, 2*DIM, DIM);
    transpose_kernel<<<(DIM*DIM + 255)/256, 256>>>(w_out, wout_t, DIM,   DIM);

    // pos convs (residual + bias)
    dw3_kernel<true, true><<<dim3((PS_X + 255)/256, BATCH*DIM), 256>>>(
        x, xp, w_pos, b_pos, HX, HX, DIM);
    dw3_kernel<true, true><<<dim3((PS_S + 255)/256, BATCH*DIM), 256>>>(
        sp, spp, w_pos, b_pos, HS, HS, DIM);

    // q path: conv1 then depthwise
    conv1_gemm<<<dim3((PS_S + 127)/128, 1, BATCH), 256>>>(wq_t, spp, tq, DIM, PS_S);
    dw3_kernel<false, false><<<dim3((PS_S + 255)/256, BATCH*DIM), 256>>>(
        tq, q, w_qdw, nullptr, HS, HS, DIM);

    // kv path: conv1 then depthwise
    conv1_gemm<<<dim3((PS_X + 127)/128, 2, BATCH), 256>>>(wkv_t, xp, tkv, 2*DIM, PS_X);
    dw3_kernel<false, false><<<dim3((PS_X + 255)/256, BATCH*2*DIM), 256>>>(
        tkv, kv, w_kvdw, nullptr, HX, HX, 2*DIM);

    // windowed attention
    attn_kernel<<<dim3(BATCH*NWIN, 4), 256>>>();

    // reverse (overlap-add / count)
    reverse_kernel<<<(BATCH*DIM*PS_S + 255)/256, 256>>>();

    // final 1x1 conv to output
    conv1_gemm<<<dim3((PS_S + 127)/128, 1, BATCH), 256>>>(wout_t, acc, out, DIM, PS_S);
}

// round 3
// speedup vs baseline: 1.4817x; 1.4817x over previous
#include <cuda_runtime.h>
#include <cstdint>

#define BATCH 2
#define DIM   128
#define HS    62
#define HX    248
#define PS_S  (HS*HS)   // 3844
#define PS_X  (HX*HX)   // 61504
#define NWIN  100       // 10x10 windows

// ---------------- scratch (static device buffers; no allocation allowed) ----
__device__ float g_xp  [BATCH*DIM*PS_X];        // x + pos-conv
__device__ float g_spp [BATCH*DIM*PS_S];        // sp + pos-conv
__device__ float g_tkv [BATCH*2*DIM*PS_X];      // conv1(kv) pre-dw
__device__ float g_kv  [BATCH*2*DIM*PS_X];      // kv after depthwise
__device__ float g_tq  [BATCH*DIM*PS_S];        // conv1(q) pre-dw
__device__ float g_q   [BATCH*DIM*PS_S];        // q after depthwise
__device__ float g_win [BATCH*NWIN*DIM*64];     // attention output windows
__device__ float g_acc [BATCH*DIM*PS_S];        // reverse output
__device__ float g_wq_t  [DIM*DIM];             // transposed weights (K-major)
__device__ float g_wkv_t [DIM*2*DIM];
__device__ float g_wout_t[DIM*DIM];

__device__ __forceinline__ uint32_t f2tf32(float f) {
    uint32_t u;
    asm("cvt.rna.tf32.f32 %0, %1;" : "=r"(u) : "f"(f));
    return u;
}

// ---------------- weight transpose: wt[c*O+o] = w[o*C+c] ---------------------
__global__ void transpose_kernel(const float* __restrict__ w, float* __restrict__ wt,
                                 int O, int C) {
    int idx = blockIdx.x * 256 + threadIdx.x;
    if (idx >= O * C) return;
    int o = idx / C, c = idx % C;
    wt[c * O + o] = w[idx];
}

// ---------------- depthwise 3x3, 4 px/thread (optional residual + bias) -----
template<bool RES, bool BIAS>
__global__ void dw3v_kernel(const float* __restrict__ in, float* __restrict__ out,
                            const float* __restrict__ w, const float* __restrict__ bias,
                            int H, int W, int cmod) {
    int plane = blockIdx.y;
    int nq = (W + 3) >> 2;
    int qidx = blockIdx.x * 256 + threadIdx.x;
    if (qidx >= H * nq) return;
    int y = qidx / nq, x0 = (qidx % nq) << 2;
    int c = plane % cmod;
    int HW = H * W;
    const float* ip = in + (size_t)plane * HW;
    const float* wc = w + c * 9;
    float w0[3] = {wc[0], wc[3], wc[6]};
    float w1[3] = {wc[1], wc[4], wc[7]};
    float w2[3] = {wc[2], wc[5], wc[8]};

    float a0, a1, a2, a3;
    a0 = a1 = a2 = a3 = BIAS ? bias[c] : 0.0f;
    float ctr[4] = {0.f, 0.f, 0.f, 0.f};

    bool interior = (x0 >= 1) && (x0 + 5 <= W);
#pragma unroll
    for (int ky = 0; ky < 3; ky++) {
        int yy = y + ky - 1;
        if ((unsigned)yy >= (unsigned)H) continue;
        const float* rp = ip + (size_t)yy * W;
        float v0, v1, v2, v3, v4, v5;
        if (interior) {
            v0 = rp[x0 - 1]; v1 = rp[x0]; v2 = rp[x0 + 1];
            v3 = rp[x0 + 2]; v4 = rp[x0 + 3]; v5 = rp[x0 + 4];
        } else {
            v0 = (x0 - 1 >= 0)             ? rp[x0 - 1] : 0.0f;
            v1 = (x0     < W)              ? rp[x0]     : 0.0f;
            v2 = (x0 + 1 < W)              ? rp[x0 + 1] : 0.0f;
            v3 = (x0 + 2 < W)              ? rp[x0 + 2] : 0.0f;
            v4 = (x0 + 3 < W)              ? rp[x0 + 3] : 0.0f;
            v5 = (x0 + 4 < W)              ? rp[x0 + 4] : 0.0f;
        }
        if (RES && ky == 1) { ctr[0] = v1; ctr[1] = v2; ctr[2] = v3; ctr[3] = v4; }
        float wy0 = w0[ky], wy1 = w1[ky], wy2 = w2[ky];
        a0 += v0 * wy0 + v1 * wy1 + v2 * wy2;
        a1 += v1 * wy0 + v2 * wy1 + v3 * wy2;
        a2 += v2 * wy0 + v3 * wy1 + v4 * wy2;
        a3 += v3 * wy0 + v4 * wy1 + v5 * wy2;
    }
    float* op = out + (size_t)plane * HW + (size_t)y * W + x0;
    float r[4] = {a0, a1, a2, a3};
#pragma unroll
    for (int j = 0; j < 4; j++) {
        if (x0 + j < W) op[j] = RES ? (ctr[j] + r[j]) : r[j];
    }
}

// ---------------- conv1 as tf32 tensor-core GEMM ----------------------------
// out[o,p] = sum_c Wt[c,o] * in[c,p].  C = 128 fixed.
// Block: 128(O) x 128(P), 256 threads = 8 warps (2 O-groups x 4 P-groups).
// Each warp: 64(O) x 32(P) via mma.sync.m16n8k8.tf32 (4 m-tiles x 4 n-tiles).
__global__ __launch_bounds__(256)
void conv1_gemm_tf32(const float* __restrict__ Wt, const float* __restrict__ in,
                     float* __restrict__ out, int O, int P) {
    __shared__ uint32_t Ws[8][136];   // [k][o], pad 8 -> fragment LDS conflict-free
    __shared__ uint32_t Xs[8][136];   // [k][p]

    const float* inb = in + (size_t)blockIdx.z * 128 * P;
    float* outb = out + (size_t)blockIdx.z * O * P;

    int p0 = blockIdx.x * 128;
    int o0 = blockIdx.y * 128;
    int tid = threadIdx.x;
    int lane = tid & 31, warp = tid >> 5;
    int wo = warp >> 2;      // 0..1 : O sub-tile of 64
    int wp = warp & 3;       // 0..3 : P sub-tile of 32
    int g = lane >> 2;       // groupID 0..7
    int tq = lane & 3;       // 0..3

    float c[4][4][4];
#pragma unroll
    for (int mi = 0; mi < 4; mi++)
#pragma unroll
        for (int ni = 0; ni < 4; ni++)
#pragma unroll
            for (int r = 0; r < 4; r++) c[mi][ni][r] = 0.0f;

    for (int k0 = 0; k0 < 128; k0 += 8) {
        // stage tiles (converted to tf32)
#pragma unroll
        for (int l = 0; l < 4; l++) {
            int e = tid + l * 256;
            int k = e >> 7, o = e & 127;
            Ws[k][o] = f2tf32(Wt[(size_t)(k0 + k) * O + o0 + o]);
        }
#pragma unroll
        for (int l = 0; l < 4; l++) {
            int e = tid + l * 256;
            int k = e >> 7, p = e & 127;
            int gp = p0 + p;
            Xs[k][p] = f2tf32((gp < P) ? inb[(size_t)(k0 + k) * P + gp] : 0.0f);
        }
        __syncthreads();

        // B fragments (k x n col-major): b0 at k=tq,n=g ; b1 at k=tq+4,n=g
        uint32_t bf[4][2];
#pragma unroll
        for (int ni = 0; ni < 4; ni++) {
            int col = wp * 32 + ni * 8 + g;
            bf[ni][0] = Xs[tq][col];
            bf[ni][1] = Xs[tq + 4][col];
        }
        // A fragments (m x k row-major): a0 m=g,k=tq; a1 m=g+8; a2 k=tq+4; a3 both
        uint32_t af[4][4];
#pragma unroll
        for (int mi = 0; mi < 4; mi++) {
            int row = wo * 64 + mi * 16 + g;
            af[mi][0] = Ws[tq][row];
            af[mi][1] = Ws[tq][row + 8];
            af[mi][2] = Ws[tq + 4][row];
            af[mi][3] = Ws[tq + 4][row + 8];
        }
#pragma unroll
        for (int mi = 0; mi < 4; mi++)
#pragma unroll
            for (int ni = 0; ni < 4; ni++) {
                asm volatile(
                    "mma.sync.aligned.m16n8k8.row.col.f32.tf32.tf32.f32 "
                    "{%0,%1,%2,%3}, {%4,%5,%6,%7}, {%8,%9}, {%0,%1,%2,%3};"
                    : "+f"(c[mi][ni][0]), "+f"(c[mi][ni][1]),
                      "+f"(c[mi][ni][2]), "+f"(c[mi][ni][3])
                    : "r"(af[mi][0]), "r"(af[mi][1]), "r"(af[mi][2]), "r"(af[mi][3]),
                      "r"(bf[ni][0]), "r"(bf[ni][1]));
            }
        __syncthreads();
    }

    // store: c0 (m=g, n=2tq) c1 (n+1) c2 (m=g+8) c3
#pragma unroll
    for (int mi = 0; mi < 4; mi++) {
        int row0 = o0 + wo * 64 + mi * 16 + g;
#pragma unroll
        for (int ni = 0; ni < 4; ni++) {
            int col = p0 + wp * 32 + ni * 8 + 2 * tq;
            if (col + 1 < P) {
                float* r0 = outb + (size_t)row0 * P + col;
                float* r1 = outb + (size_t)(row0 + 8) * P + col;
                r0[0] = c[mi][ni][0]; r0[1] = c[mi][ni][1];
                r1[0] = c[mi][ni][2]; r1[1] = c[mi][ni][3];
            } else {
                if (col < P) {
                    outb[(size_t)row0 * P + col] = c[mi][ni][0];
                    outb[(size_t)(row0 + 8) * P + col] = c[mi][ni][2];
                }
            }
        }
    }
}

// ---------------- windowed attention (flash-style streaming softmax) --------
__global__ __launch_bounds__(256)
void attn_kernel() {
    __shared__ float qs[64][33];
    __shared__ float ks[64][33];
    __shared__ float vs[64][33];
    __shared__ float ps[64][64];

    int bn = blockIdx.x;
    int h  = blockIdx.y;
    int b = bn / NWIN, n = bn % NWIN;
    int wh = n / 10, ww = n % 10;
    int tid = threadIdx.x, lane = tid & 31, warp = tid >> 5;

    int y0q = 6 * wh, x0q = 6 * ww;
    int y0k = 24 * wh, x0k = 24 * ww;

    const float scale = 0.17677669529663687f; // 1/sqrt(32)

    for (int e = tid; e < 2048; e += 256) {
        int c = e >> 6, i = e & 63;
        int dy = i >> 3, dx = i & 7;
        qs[i][c] = g_q[((size_t)(b * DIM + h * 32 + c) * HS + y0q + dy) * HS + x0q + dx] * scale;
    }

    float acc[8], m[8], l[8];
#pragma unroll
    for (int r = 0; r < 8; r++) { acc[r] = 0.0f; m[r] = -1e30f; l[r] = 0.0f; }
    __syncthreads();

    for (int c0 = 0; c0 < 1024; c0 += 64) {
        for (int e = tid; e < 2048; e += 256) {
            int ch = e >> 6, j = e & 63;
            int kj = c0 + j;
            int ky = y0k + (kj >> 5), kx = x0k + (kj & 31);
            ks[j][ch] = g_kv[((size_t)(b * 2 * DIM + h * 32 + ch) * HX + ky) * HX + kx];
            vs[j][ch] = g_kv[((size_t)(b * 2 * DIM + DIM + h * 32 + ch) * HX + ky) * HX + kx];
        }
        __syncthreads();

#pragma unroll
        for (int r = 0; r < 8; r++) {
            int i = warp * 8 + r;
            float s0 = 0.0f, s1 = 0.0f;
#pragma unroll
            for (int c = 0; c < 32; c++) {
                float qv = qs[i][c];
                s0 += qv * ks[lane][c];
                s1 += qv * ks[lane + 32][c];
            }
            float mx = fmaxf(s0, s1);
#pragma unroll
            for (int off = 16; off; off >>= 1)
                mx = fmaxf(mx, __shfl_xor_sync(0xFFFFFFFFu, mx, off));
            float mnew = fmaxf(m[r], mx);
            float corr = __expf(m[r] - mnew);
            float p0 = __expf(s0 - mnew);
            float p1 = __expf(s1 - mnew);
            float psum = p0 + p1;
#pragma unroll
            for (int off = 16; off; off >>= 1)
                psum += __shfl_xor_sync(0xFFFFFFFFu, psum, off);
            m[r] = mnew;
            l[r] = l[r] * corr + psum;
            acc[r] *= corr;
            ps[i][lane] = p0;
            ps[i][lane + 32] = p1;
        }
        __syncwarp();

#pragma unroll 4
        for (int j = 0; j < 64; j++) {
            float vv = vs[j][lane];
#pragma unroll
            for (int r = 0; r < 8; r++)
                acc[r] += ps[warp * 8 + r][j] * vv;
        }
        __syncthreads();
    }

#pragma unroll
    for (int r = 0; r < 8; r++) {
        int i = warp * 8 + r;
        g_win[((size_t)bn * DIM + h * 32 + lane) * 64 + i] = acc[r] / l[r];
    }
}

// ---------------- reverse (overlap-add with count normalization) ------------
__global__ void reverse_kernel() {
    int idx = blockIdx.x * 256 + threadIdx.x;
    if (idx >= BATCH * DIM * PS_S) return;
    int x = idx % HS;
    int y = (idx / HS) % HS;
    int c = (idx / PS_S) % DIM;
    int b = idx / (PS_S * DIM);

    int wlo = max(0, (y - 2) / 6), whi = min(9, y / 6);
    int vlo = max(0, (x - 2) / 6), vhi = min(9, x / 6);
    float s = 0.0f;
    for (int wh = wlo; wh <= whi; wh++) {
        int dy = y - 6 * wh;
        for (int ww = vlo; ww <= vhi; ww++) {
            int dx = x - 6 * ww;
            int n = wh * 10 + ww;
            s += g_win[((size_t)(b * NWIN + n) * DIM + c) * 64 + dy * 8 + dx];
        }
    }
    int cnt = (whi - wlo + 1) * (vhi - vlo + 1);
    g_acc[idx] = s / (float)cnt;
}

// ---------------- launch --------------------------------------------------
extern "C" void kernel_launch(void* const* d_in, const int* in_sizes, int n_in,
                              void* d_out, int out_size) {
    const float* x     = (const float*)d_in[0];
    const float* sp    = (const float*)d_in[1];
    const float* w_pos = (const float*)d_in[2];
    const float* b_pos = (const float*)d_in[3];
    const float* w_q   = (const float*)d_in[4];
    const float* w_qdw = (const float*)d_in[5];
    const float* w_kv  = (const float*)d_in[6];
    const float* w_kvdw= (const float*)d_in[7];
    const float* w_out = (const float*)d_in[8];
    float* out = (float*)d_out;

    float *xp, *spp, *tkv, *kv, *tq, *q, *acc, *wq_t, *wkv_t, *wout_t;
    cudaGetSymbolAddress((void**)&xp,    g_xp);
    cudaGetSymbolAddress((void**)&spp,   g_spp);
    cudaGetSymbolAddress((void**)&tkv,   g_tkv);
    cudaGetSymbolAddress((void**)&kv,    g_kv);
    cudaGetSymbolAddress((void**)&tq,    g_tq);
    cudaGetSymbolAddress((void**)&q,     g_q);
    cudaGetSymbolAddress((void**)&acc,   g_acc);
    cudaGetSymbolAddress((void**)&wq_t,  g_wq_t);
    cudaGetSymbolAddress((void**)&wkv_t, g_wkv_t);
    cudaGetSymbolAddress((void**)&wout_t,g_wout_t);

    // weight transposes (K-major for GEMM)
    transpose_kernel<<<(DIM*DIM + 255)/256, 256>>>(w_q,   wq_t,   DIM,   DIM);
    transpose_kernel<<<(2*DIM*DIM + 255)/256, 256>>>(w_kv, wkv_t, 2*DIM, DIM);
    transpose_kernel<<<(DIM*DIM + 255)/256, 256>>>(w_out, wout_t, DIM,   DIM);

    int nqx = (HX + 3) / 4, nqs = (HS + 3) / 4;

    // pos convs (residual + bias)
    dw3v_kernel<true, true><<<dim3((HX*nqx + 255)/256, BATCH*DIM), 256>>>(
        x, xp, w_pos, b_pos, HX, HX, DIM);
    dw3v_kernel<true, true><<<dim3((HS*nqs + 255)/256, BATCH*DIM), 256>>>(
        sp, spp, w_pos, b_pos, HS, HS, DIM);

    // q path
    conv1_gemm_tf32<<<dim3((PS_S + 127)/128, 1, BATCH), 256>>>(wq_t, spp, tq, DIM, PS_S);
    dw3v_kernel<false, false><<<dim3((HS*nqs + 255)/256, BATCH*DIM), 256>>>(
        tq, q, w_qdw, nullptr, HS, HS, DIM);

    // kv path
    conv1_gemm_tf32<<<dim3((PS_X + 127)/128, 2, BATCH), 256>>>(wkv_t, xp, tkv, 2*DIM, PS_X);
    dw3v_kernel<false, false><<<dim3((HX*nqx + 255)/256, BATCH*2*DIM), 256>>>(
        tkv, kv, w_kvdw, nullptr, HX, HX, 2*DIM);

    // windowed attention
    attn_kernel<<<dim3(BATCH*NWIN, 4), 256>>>();

    // reverse
    reverse_kernel<<<(BATCH*DIM*PS_S + 255)/256, 256>>>();

    // final 1x1 conv
    conv1_gemm_tf32<<<dim3((PS_S + 127)/128, 1, BATCH), 256>>>(wout_t, acc, out, DIM, PS_S);
}

// round 4
// speedup vs baseline: 1.8413x; 1.2427x over previous
#include <cuda_runtime.h>
#include <cstdint>

#define BATCH 2
#define DIM   128
#define HS    62
#define HX    248
#define PS_S  (HS*HS)   // 3844
#define PS_X  (HX*HX)   // 61504
#define NWIN  100       // 10x10 windows

// ---------------- scratch (static device buffers; no allocation allowed) ----
__device__ float g_xp  [BATCH*DIM*PS_X];        // x + pos-conv
__device__ float g_spp [BATCH*DIM*PS_S];        // sp + pos-conv
__device__ float g_tkv [BATCH*2*DIM*PS_X];      // conv1(kv) pre-dw
__device__ float g_kv  [BATCH*2*DIM*PS_X];      // kv after depthwise
__device__ float g_tq  [BATCH*DIM*PS_S];        // conv1(q) pre-dw
__device__ float g_q   [BATCH*DIM*PS_S];        // q after depthwise
__device__ float g_win [BATCH*NWIN*DIM*64];     // attention output windows
__device__ float g_acc [BATCH*DIM*PS_S];        // reverse output
__device__ float g_wq_t  [DIM*DIM];             // transposed weights (K-major)
__device__ float g_wkv_t [DIM*2*DIM];
__device__ float g_wout_t[DIM*DIM];

__device__ __forceinline__ uint32_t f2tf32(float f) {
    uint32_t u;
    asm("cvt.rna.tf32.f32 %0, %1;" : "=r"(u) : "f"(f));
    return u;
}

#define MMA_TF32(C0,C1,C2,C3,A0,A1,A2,A3,B0,B1)                               \
    asm volatile(                                                             \
        "mma.sync.aligned.m16n8k8.row.col.f32.tf32.tf32.f32 "                 \
        "{%0,%1,%2,%3}, {%4,%5,%6,%7}, {%8,%9}, {%0,%1,%2,%3};"               \
        : "+f"(C0), "+f"(C1), "+f"(C2), "+f"(C3)                              \
        : "r"(A0), "r"(A1), "r"(A2), "r"(A3), "r"(B0), "r"(B1))

// ---------------- weight transpose: wt[c*O+o] = w[o*C+c] ---------------------
__global__ void transpose_kernel(const float* __restrict__ w, float* __restrict__ wt,
                                 int O, int C) {
    int idx = blockIdx.x * 256 + threadIdx.x;
    if (idx >= O * C) return;
    int o = idx / C, c = idx % C;
    wt[c * O + o] = w[idx];
}

// ---------------- depthwise 3x3, 4 px/thread (optional residual + bias) -----
template<bool RES, bool BIAS>
__global__ void dw3v_kernel(const float* __restrict__ in, float* __restrict__ out,
                            const float* __restrict__ w, const float* __restrict__ bias,
                            int H, int W, int cmod) {
    int plane = blockIdx.y;
    int nq = (W + 3) >> 2;
    int qidx = blockIdx.x * 256 + threadIdx.x;
    if (qidx >= H * nq) return;
    int y = qidx / nq, x0 = (qidx % nq) << 2;
    int c = plane % cmod;
    int HW = H * W;
    const float* ip = in + (size_t)plane * HW;
    const float* wc = w + c * 9;
    float w0[3] = {wc[0], wc[3], wc[6]};
    float w1[3] = {wc[1], wc[4], wc[7]};
    float w2[3] = {wc[2], wc[5], wc[8]};

    float a0, a1, a2, a3;
    a0 = a1 = a2 = a3 = BIAS ? bias[c] : 0.0f;
    float ctr[4] = {0.f, 0.f, 0.f, 0.f};

    bool interior = (x0 >= 1) && (x0 + 5 <= W);
#pragma unroll
    for (int ky = 0; ky < 3; ky++) {
        int yy = y + ky - 1;
        if ((unsigned)yy >= (unsigned)H) continue;
        const float* rp = ip + (size_t)yy * W;
        float v0, v1, v2, v3, v4, v5;
        if (interior) {
            v0 = rp[x0 - 1]; v1 = rp[x0]; v2 = rp[x0 + 1];
            v3 = rp[x0 + 2]; v4 = rp[x0 + 3]; v5 = rp[x0 + 4];
        } else {
            v0 = (x0 - 1 >= 0)             ? rp[x0 - 1] : 0.0f;
            v1 = (x0     < W)              ? rp[x0]     : 0.0f;
            v2 = (x0 + 1 < W)              ? rp[x0 + 1] : 0.0f;
            v3 = (x0 + 2 < W)              ? rp[x0 + 2] : 0.0f;
            v4 = (x0 + 3 < W)              ? rp[x0 + 3] : 0.0f;
            v5 = (x0 + 4 < W)              ? rp[x0 + 4] : 0.0f;
        }
        if (RES && ky == 1) { ctr[0] = v1; ctr[1] = v2; ctr[2] = v3; ctr[3] = v4; }
        float wy0 = w0[ky], wy1 = w1[ky], wy2 = w2[ky];
        a0 += v0 * wy0 + v1 * wy1 + v2 * wy2;
        a1 += v1 * wy0 + v2 * wy1 + v3 * wy2;
        a2 += v2 * wy0 + v3 * wy1 + v4 * wy2;
        a3 += v3 * wy0 + v4 * wy1 + v5 * wy2;
    }
    float* op = out + (size_t)plane * HW + (size_t)y * W + x0;
    float r[4] = {a0, a1, a2, a3};
#pragma unroll
    for (int j = 0; j < 4; j++) {
        if (x0 + j < W) op[j] = RES ? (ctr[j] + r[j]) : r[j];
    }
}

// ---------------- conv1 as tf32 tensor-core GEMM ----------------------------
__global__ __launch_bounds__(256)
void conv1_gemm_tf32(const float* __restrict__ Wt, const float* __restrict__ in,
                     float* __restrict__ out, int O, int P) {
    __shared__ uint32_t Ws[8][136];
    __shared__ uint32_t Xs[8][136];

    const float* inb = in + (size_t)blockIdx.z * 128 * P;
    float* outb = out + (size_t)blockIdx.z * O * P;

    int p0 = blockIdx.x * 128;
    int o0 = blockIdx.y * 128;
    int tid = threadIdx.x;
    int lane = tid & 31, warp = tid >> 5;
    int wo = warp >> 2;
    int wp = warp & 3;
    int g = lane >> 2;
    int tq = lane & 3;

    float c[4][4][4];
#pragma unroll
    for (int mi = 0; mi < 4; mi++)
#pragma unroll
        for (int ni = 0; ni < 4; ni++)
#pragma unroll
            for (int r = 0; r < 4; r++) c[mi][ni][r] = 0.0f;

    for (int k0 = 0; k0 < 128; k0 += 8) {
#pragma unroll
        for (int l = 0; l < 4; l++) {
            int e = tid + l * 256;
            int k = e >> 7, o = e & 127;
            Ws[k][o] = f2tf32(Wt[(size_t)(k0 + k) * O + o0 + o]);
        }
#pragma unroll
        for (int l = 0; l < 4; l++) {
            int e = tid + l * 256;
            int k = e >> 7, p = e & 127;
            int gp = p0 + p;
            Xs[k][p] = f2tf32((gp < P) ? inb[(size_t)(k0 + k) * P + gp] : 0.0f);
        }
        __syncthreads();

        uint32_t bf[4][2];
#pragma unroll
        for (int ni = 0; ni < 4; ni++) {
            int col = wp * 32 + ni * 8 + g;
            bf[ni][0] = Xs[tq][col];
            bf[ni][1] = Xs[tq + 4][col];
        }
        uint32_t af[4][4];
#pragma unroll
        for (int mi = 0; mi < 4; mi++) {
            int row = wo * 64 + mi * 16 + g;
            af[mi][0] = Ws[tq][row];
            af[mi][1] = Ws[tq][row + 8];
            af[mi][2] = Ws[tq + 4][row];
            af[mi][3] = Ws[tq + 4][row + 8];
        }
#pragma unroll
        for (int mi = 0; mi < 4; mi++)
#pragma unroll
            for (int ni = 0; ni < 4; ni++)
                MMA_TF32(c[mi][ni][0], c[mi][ni][1], c[mi][ni][2], c[mi][ni][3],
                         af[mi][0], af[mi][1], af[mi][2], af[mi][3],
                         bf[ni][0], bf[ni][1]);
        __syncthreads();
    }

#pragma unroll
    for (int mi = 0; mi < 4; mi++) {
        int row0 = o0 + wo * 64 + mi * 16 + g;
#pragma unroll
        for (int ni = 0; ni < 4; ni++) {
            int col = p0 + wp * 32 + ni * 8 + 2 * tq;
            if (col + 1 < P) {
                float* r0 = outb + (size_t)row0 * P + col;
                float* r1 = outb + (size_t)(row0 + 8) * P + col;
                r0[0] = c[mi][ni][0]; r0[1] = c[mi][ni][1];
                r1[0] = c[mi][ni][2]; r1[1] = c[mi][ni][3];
            } else {
                if (col < P) {
                    outb[(size_t)row0 * P + col] = c[mi][ni][0];
                    outb[(size_t)(row0 + 8) * P + col] = c[mi][ni][2];
                }
            }
        }
    }
}

// ---------------- windowed attention: tf32 mma + streaming softmax ----------
// block = (bn, head), 128 threads = 4 warps. Warp w owns q rows [16w, 16w+16).
// S = Q K^T via m16n8k8 (A=Q, B=K), softmax on C-frags, O += P V via m16n8k8.
__global__ __launch_bounds__(128)
void attn_mma_kernel() {
    __shared__ uint32_t qs[64][33];    // [q pos][ch]   tf32, scale folded
    __shared__ uint32_t ks[64][33];    // [kv pos][ch]  tf32
    __shared__ uint32_t vs[64][33];    // [kv pos][ch]  tf32
    __shared__ uint32_t ps[4][16][68]; // per-warp P tile [q row][kv col] tf32

    int bn = blockIdx.x;
    int h  = blockIdx.y;
    int b = bn / NWIN, n = bn % NWIN;
    int wh = n / 10, ww = n % 10;
    int tid = threadIdx.x, lane = tid & 31, warp = tid >> 5;
    int g = lane >> 2, tq = lane & 3;

    int y0q = 6 * wh, x0q = 6 * ww;
    int y0k = 24 * wh, x0k = 24 * ww;
    const float scale = 0.17677669529663687f; // 1/sqrt(32)

    // stage q (64 pos x 32 ch), fold scale
    for (int e = tid; e < 2048; e += 128) {
        int c = e >> 6, i = e & 63;
        int dy = i >> 3, dx = i & 7;
        qs[i][c] = f2tf32(
            g_q[((size_t)(b * DIM + h * 32 + c) * HS + y0q + dy) * HS + x0q + dx] * scale);
    }

    float oacc[4][4];
#pragma unroll
    for (int ni = 0; ni < 4; ni++)
#pragma unroll
        for (int r = 0; r < 4; r++) oacc[ni][r] = 0.0f;
    float mrow0 = -1e30f, mrow1 = -1e30f, lrow0 = 0.0f, lrow1 = 0.0f;

    int m0 = warp * 16;
    __syncthreads();

    for (int c0 = 0; c0 < 1024; c0 += 64) {
        // stage K/V chunk (64 pos x 32 ch)
        for (int e = tid; e < 2048; e += 128) {
            int ch = e >> 6, j = e & 63;
            int kj = c0 + j;
            int ky = y0k + (kj >> 5), kx = x0k + (kj & 31);
            ks[j][ch] = f2tf32(g_kv[((size_t)(b * 2 * DIM + h * 32 + ch) * HX + ky) * HX + kx]);
            vs[j][ch] = f2tf32(g_kv[((size_t)(b * 2 * DIM + DIM + h * 32 + ch) * HX + ky) * HX + kx]);
        }
        __syncthreads();

        // ---- S = Q K^T  (16 x 64 per warp) ----
        float sc[8][4];
#pragma unroll
        for (int ni = 0; ni < 8; ni++)
#pragma unroll
            for (int r = 0; r < 4; r++) sc[ni][r] = 0.0f;

#pragma unroll
        for (int k0 = 0; k0 < 4; k0++) {
            uint32_t a0 = qs[m0 + g][k0 * 8 + tq];
            uint32_t a1 = qs[m0 + g + 8][k0 * 8 + tq];
            uint32_t a2 = qs[m0 + g][k0 * 8 + tq + 4];
            uint32_t a3 = qs[m0 + g + 8][k0 * 8 + tq + 4];
#pragma unroll
            for (int ni = 0; ni < 8; ni++) {
                uint32_t b0 = ks[ni * 8 + g][k0 * 8 + tq];
                uint32_t b1 = ks[ni * 8 + g][k0 * 8 + tq + 4];
                MMA_TF32(sc[ni][0], sc[ni][1], sc[ni][2], sc[ni][3],
                         a0, a1, a2, a3, b0, b1);
            }
        }

        // ---- streaming softmax on fragments ----
        float mx0 = -1e30f, mx1 = -1e30f;
#pragma unroll
        for (int ni = 0; ni < 8; ni++) {
            mx0 = fmaxf(mx0, fmaxf(sc[ni][0], sc[ni][1]));
            mx1 = fmaxf(mx1, fmaxf(sc[ni][2], sc[ni][3]));
        }
#pragma unroll
        for (int off = 1; off <= 2; off <<= 1) {
            mx0 = fmaxf(mx0, __shfl_xor_sync(0xFFFFFFFFu, mx0, off));
            mx1 = fmaxf(mx1, __shfl_xor_sync(0xFFFFFFFFu, mx1, off));
        }
        float mn0 = fmaxf(mrow0, mx0), mn1 = fmaxf(mrow1, mx1);
        float cor0 = __expf(mrow0 - mn0), cor1 = __expf(mrow1 - mn1);
        mrow0 = mn0; mrow1 = mn1;

        float s0 = 0.0f, s1 = 0.0f;
#pragma unroll
        for (int ni = 0; ni < 8; ni++) {
            sc[ni][0] = __expf(sc[ni][0] - mn0);
            sc[ni][1] = __expf(sc[ni][1] - mn0);
            sc[ni][2] = __expf(sc[ni][2] - mn1);
            sc[ni][3] = __expf(sc[ni][3] - mn1);
            s0 += sc[ni][0] + sc[ni][1];
            s1 += sc[ni][2] + sc[ni][3];
        }
#pragma unroll
        for (int off = 1; off <= 2; off <<= 1) {
            s0 += __shfl_xor_sync(0xFFFFFFFFu, s0, off);
            s1 += __shfl_xor_sync(0xFFFFFFFFu, s1, off);
        }
        lrow0 = lrow0 * cor0 + s0;
        lrow1 = lrow1 * cor1 + s1;
#pragma unroll
        for (int ni = 0; ni < 4; ni++) {
            oacc[ni][0] *= cor0; oacc[ni][1] *= cor0;
            oacc[ni][2] *= cor1; oacc[ni][3] *= cor1;
        }

        // ---- P -> smem (tf32), then O += P V ----
#pragma unroll
        for (int ni = 0; ni < 8; ni++) {
            ps[warp][g][ni * 8 + 2 * tq]         = f2tf32(sc[ni][0]);
            ps[warp][g][ni * 8 + 2 * tq + 1]     = f2tf32(sc[ni][1]);
            ps[warp][g + 8][ni * 8 + 2 * tq]     = f2tf32(sc[ni][2]);
            ps[warp][g + 8][ni * 8 + 2 * tq + 1] = f2tf32(sc[ni][3]);
        }
        __syncwarp();

#pragma unroll
        for (int kk = 0; kk < 8; kk++) {
            uint32_t a0 = ps[warp][g][kk * 8 + tq];
            uint32_t a1 = ps[warp][g + 8][kk * 8 + tq];
            uint32_t a2 = ps[warp][g][kk * 8 + tq + 4];
            uint32_t a3 = ps[warp][g + 8][kk * 8 + tq + 4];
#pragma unroll
            for (int ni = 0; ni < 4; ni++) {
                uint32_t b0 = vs[kk * 8 + tq][ni * 8 + g];
                uint32_t b1 = vs[kk * 8 + tq + 4][ni * 8 + g];
                MMA_TF32(oacc[ni][0], oacc[ni][1], oacc[ni][2], oacc[ni][3],
                         a0, a1, a2, a3, b0, b1);
            }
        }
        __syncthreads();
    }

    float inv0 = 1.0f / lrow0, inv1 = 1.0f / lrow1;
#pragma unroll
    for (int ni = 0; ni < 4; ni++) {
        int col = h * 32 + ni * 8 + 2 * tq;
        size_t base = (size_t)bn * DIM;
        g_win[(base + col) * 64 + m0 + g]         = oacc[ni][0] * inv0;
        g_win[(base + col + 1) * 64 + m0 + g]     = oacc[ni][1] * inv0;
        g_win[(base + col) * 64 + m0 + g + 8]     = oacc[ni][2] * inv1;
        g_win[(base + col + 1) * 64 + m0 + g + 8] = oacc[ni][3] * inv1;
    }
}

// ---------------- reverse (overlap-add with count normalization) ------------
__global__ void reverse_kernel() {
    int idx = blockIdx.x * 256 + threadIdx.x;
    if (idx >= BATCH * DIM * PS_S) return;
    int x = idx % HS;
    int y = (idx / HS) % HS;
    int c = (idx / PS_S) % DIM;
    int b = idx / (PS_S * DIM);

    int wlo = max(0, (y - 2) / 6), whi = min(9, y / 6);
    int vlo = max(0, (x - 2) / 6), vhi = min(9, x / 6);
    float s = 0.0f;
    for (int wh = wlo; wh <= whi; wh++) {
        int dy = y - 6 * wh;
        for (int ww = vlo; ww <= vhi; ww++) {
            int dx = x - 6 * ww;
            int n = wh * 10 + ww;
            s += g_win[((size_t)(b * NWIN + n) * DIM + c) * 64 + dy * 8 + dx];
        }
    }
    int cnt = (whi - wlo + 1) * (vhi - vlo + 1);
    g_acc[idx] = s / (float)cnt;
}

// ---------------- launch --------------------------------------------------
extern "C" void kernel_launch(void* const* d_in, const int* in_sizes, int n_in,
                              void* d_out, int out_size) {
    const float* x     = (const float*)d_in[0];
    const float* sp    = (const float*)d_in[1];
    const float* w_pos = (const float*)d_in[2];
    const float* b_pos = (const float*)d_in[3];
    const float* w_q   = (const float*)d_in[4];
    const float* w_qdw = (const float*)d_in[5];
    const float* w_kv  = (const float*)d_in[6];
    const float* w_kvdw= (const float*)d_in[7];
    const float* w_out = (const float*)d_in[8];
    float* out = (float*)d_out;

    float *xp, *spp, *tkv, *kv, *tq, *q, *acc, *wq_t, *wkv_t, *wout_t;
    cudaGetSymbolAddress((void**)&xp,    g_xp);
    cudaGetSymbolAddress((void**)&spp,   g_spp);
    cudaGetSymbolAddress((void**)&tkv,   g_tkv);
    cudaGetSymbolAddress((void**)&kv,    g_kv);
    cudaGetSymbolAddress((void**)&tq,    g_tq);
    cudaGetSymbolAddress((void**)&q,     g_q);
    cudaGetSymbolAddress((void**)&acc,   g_acc);
    cudaGetSymbolAddress((void**)&wq_t,  g_wq_t);
    cudaGetSymbolAddress((void**)&wkv_t, g_wkv_t);
    cudaGetSymbolAddress((void**)&wout_t,g_wout_t);

    transpose_kernel<<<(DIM*DIM + 255)/256, 256>>>(w_q,   wq_t,   DIM,   DIM);
    transpose_kernel<<<(2*DIM*DIM + 255)/256, 256>>>(w_kv, wkv_t, 2*DIM, DIM);
    transpose_kernel<<<(DIM*DIM + 255)/256, 256>>>(w_out, wout_t, DIM,   DIM);

    int nqx = (HX + 3) / 4, nqs = (HS + 3) / 4;

    dw3v_kernel<true, true><<<dim3((HX*nqx + 255)/256, BATCH*DIM), 256>>>(
        x, xp, w_pos, b_pos, HX, HX, DIM);
    dw3v_kernel<true, true><<<dim3((HS*nqs + 255)/256, BATCH*DIM), 256>>>(
        sp, spp, w_pos, b_pos, HS, HS, DIM);

    conv1_gemm_tf32<<<dim3((PS_S + 127)/128, 1, BATCH), 256>>>(wq_t, spp, tq, DIM, PS_S);
    dw3v_kernel<false, false><<<dim3((HS*nqs + 255)/256, BATCH*DIM), 256>>>(
        tq, q, w_qdw, nullptr, HS, HS, DIM);

    conv1_gemm_tf32<<<dim3((PS_X + 127)/128, 2, BATCH), 256>>>(wkv_t, xp, tkv, 2*DIM, PS_X);
    dw3v_kernel<false, false><<<dim3((HX*nqx + 255)/256, BATCH*2*DIM), 256>>>(
        tkv, kv, w_kvdw, nullptr, HX, HX, 2*DIM);

    attn_mma_kernel<<<dim3(BATCH*NWIN, 4), 128>>>();

    reverse_kernel<<<(BATCH*DIM*PS_S + 255)/256, 256>>>();

    conv1_gemm_tf32<<<dim3((PS_S + 127)/128, 1, BATCH), 256>>>(wout_t, acc, out, DIM, PS_S);
}

// round 5
// speedup vs baseline: 2.5214x; 1.3694x over previous
#include <cuda_runtime.h>
#include <cstdint>

#define BATCH 2
#define DIM   128
#define HS    62
#define HX    248
#define PS_S  (HS*HS)   // 3844
#define PS_X  (HX*HX)   // 61504
#define NWIN  100       // 10x10 windows

// ---------------- scratch (static device buffers; no allocation allowed) ----
__device__ float g_xp  [BATCH*DIM*PS_X];
__device__ float g_spp [BATCH*DIM*PS_S];
__device__ float g_tkv [BATCH*2*DIM*PS_X];
__device__ float g_kv  [BATCH*2*DIM*PS_X];
__device__ float g_tq  [BATCH*DIM*PS_S];
__device__ float g_q   [BATCH*DIM*PS_S];
__device__ float g_win [BATCH*NWIN*DIM*64];
__device__ float g_acc [BATCH*DIM*PS_S];
__device__ float g_wq_t  [DIM*DIM];
__device__ float g_wkv_t [DIM*2*DIM];
__device__ float g_wout_t[DIM*DIM];

__device__ __forceinline__ uint32_t f2tf32(float f) {
    uint32_t u;
    asm("cvt.rna.tf32.f32 %0, %1;" : "=r"(u) : "f"(f));
    return u;
}

#define MMA_TF32(C0,C1,C2,C3,A0,A1,A2,A3,B0,B1)                               \
    asm volatile(                                                             \
        "mma.sync.aligned.m16n8k8.row.col.f32.tf32.tf32.f32 "                 \
        "{%0,%1,%2,%3}, {%4,%5,%6,%7}, {%8,%9}, {%0,%1,%2,%3};"               \
        : "+f"(C0), "+f"(C1), "+f"(C2), "+f"(C3)                              \
        : "r"(A0), "r"(A1), "r"(A2), "r"(A3), "r"(B0), "r"(B1))

// ---------------- weight transpose ------------------------------------------
__global__ void transpose_kernel(const float* __restrict__ w, float* __restrict__ wt,
                                 int O, int C) {
    int idx = blockIdx.x * 256 + threadIdx.x;
    if (idx >= O * C) return;
    int o = idx / C, c = idx % C;
    wt[c * O + o] = w[idx];
}

// ---------------- depthwise 3x3, 4x4 px/thread ------------------------------
template<bool RES, bool BIAS>
__global__ void dw3q_kernel(const float* __restrict__ in, float* __restrict__ out,
                            const float* __restrict__ w, const float* __restrict__ bias,
                            int H, int W, int cmod) {
    int plane = blockIdx.y;
    int nqx = (W + 3) >> 2, nqy = (H + 3) >> 2;
    int qidx = blockIdx.x * 256 + threadIdx.x;
    if (qidx >= nqx * nqy) return;
    int y0 = (qidx / nqx) << 2, x0 = (qidx % nqx) << 2;
    int c = plane % cmod;
    int HW = H * W;
    const float* ip = in + (size_t)plane * HW;
    const float* wc = w + c * 9;
    float w0[3] = {wc[0], wc[3], wc[6]};
    float w1[3] = {wc[1], wc[4], wc[7]};
    float w2[3] = {wc[2], wc[5], wc[8]};

    float acc[4][4];
    float ctr[4][4];
    float binit = BIAS ? bias[c] : 0.0f;
#pragma unroll
    for (int r = 0; r < 4; r++)
#pragma unroll
        for (int j = 0; j < 4; j++) { acc[r][j] = binit; ctr[r][j] = 0.0f; }

    bool xint = (x0 >= 1) && (x0 + 5 <= W);
#pragma unroll
    for (int iy = 0; iy < 6; iy++) {
        int yy = y0 + iy - 1;
        if ((unsigned)yy >= (unsigned)H) continue;
        const float* rp = ip + (size_t)yy * W;
        float v[6];
        if (xint) {
#pragma unroll
            for (int i = 0; i < 6; i++) v[i] = rp[x0 - 1 + i];
        } else {
#pragma unroll
            for (int i = 0; i < 6; i++) {
                int xx = x0 - 1 + i;
                v[i] = ((unsigned)xx < (unsigned)W) ? rp[xx] : 0.0f;
            }
        }
        if (RES && iy >= 1 && iy <= 4) {
            int r = iy - 1;
#pragma unroll
            for (int j = 0; j < 4; j++) ctr[r][j] = v[j + 1];
        }
#pragma unroll
        for (int r = 0; r < 4; r++) {
            int k = iy - r;
            if (k < 0 || k > 2) continue;
            float wy0 = w0[k], wy1 = w1[k], wy2 = w2[k];
#pragma unroll
            for (int j = 0; j < 4; j++)
                acc[r][j] += v[j] * wy0 + v[j + 1] * wy1 + v[j + 2] * wy2;
        }
    }
#pragma unroll
    for (int r = 0; r < 4; r++) {
        int yo = y0 + r;
        if (yo >= H) break;
        float* op = out + (size_t)plane * HW + (size_t)yo * W;
#pragma unroll
        for (int j = 0; j < 4; j++) {
            int xo = x0 + j;
            if (xo < W) op[xo] = RES ? (ctr[r][j] + acc[r][j]) : acc[r][j];
        }
    }
}

// ---------------- conv1 as tf32 tensor-core GEMM ----------------------------
__global__ __launch_bounds__(256)
void conv1_gemm_tf32(const float* __restrict__ Wt, const float* __restrict__ in,
                     float* __restrict__ out, int O, int P) {
    __shared__ uint32_t Ws[8][136];
    __shared__ uint32_t Xs[8][136];

    const float* inb = in + (size_t)blockIdx.z * 128 * P;
    float* outb = out + (size_t)blockIdx.z * O * P;

    int p0 = blockIdx.x * 128;
    int o0 = blockIdx.y * 128;
    int tid = threadIdx.x;
    int lane = tid & 31, warp = tid >> 5;
    int wo = warp >> 2;
    int wp = warp & 3;
    int g = lane >> 2;
    int tq = lane & 3;

    float c[4][4][4];
#pragma unroll
    for (int mi = 0; mi < 4; mi++)
#pragma unroll
        for (int ni = 0; ni < 4; ni++)
#pragma unroll
            for (int r = 0; r < 4; r++) c[mi][ni][r] = 0.0f;

    for (int k0 = 0; k0 < 128; k0 += 8) {
#pragma unroll
        for (int l = 0; l < 4; l++) {
            int e = tid + l * 256;
            int k = e >> 7, o = e & 127;
            Ws[k][o] = f2tf32(Wt[(size_t)(k0 + k) * O + o0 + o]);
        }
#pragma unroll
        for (int l = 0; l < 4; l++) {
            int e = tid + l * 256;
            int k = e >> 7, p = e & 127;
            int gp = p0 + p;
            Xs[k][p] = f2tf32((gp < P) ? inb[(size_t)(k0 + k) * P + gp] : 0.0f);
        }
        __syncthreads();

        uint32_t bf[4][2];
#pragma unroll
        for (int ni = 0; ni < 4; ni++) {
            int col = wp * 32 + ni * 8 + g;
            bf[ni][0] = Xs[tq][col];
            bf[ni][1] = Xs[tq + 4][col];
        }
        uint32_t af[4][4];
#pragma unroll
        for (int mi = 0; mi < 4; mi++) {
            int row = wo * 64 + mi * 16 + g;
            af[mi][0] = Ws[tq][row];
            af[mi][1] = Ws[tq][row + 8];
            af[mi][2] = Ws[tq + 4][row];
            af[mi][3] = Ws[tq + 4][row + 8];
        }
#pragma unroll
        for (int mi = 0; mi < 4; mi++)
#pragma unroll
            for (int ni = 0; ni < 4; ni++)
                MMA_TF32(c[mi][ni][0], c[mi][ni][1], c[mi][ni][2], c[mi][ni][3],
                         af[mi][0], af[mi][1], af[mi][2], af[mi][3],
                         bf[ni][0], bf[ni][1]);
        __syncthreads();
    }

#pragma unroll
    for (int mi = 0; mi < 4; mi++) {
        int row0 = o0 + wo * 64 + mi * 16 + g;
#pragma unroll
        for (int ni = 0; ni < 4; ni++) {
            int col = p0 + wp * 32 + ni * 8 + 2 * tq;
            if (col + 1 < P) {
                float* r0 = outb + (size_t)row0 * P + col;
                float* r1 = outb + (size_t)(row0 + 8) * P + col;
                r0[0] = c[mi][ni][0]; r0[1] = c[mi][ni][1];
                r1[0] = c[mi][ni][2]; r1[1] = c[mi][ni][3];
            } else {
                if (col < P) {
                    outb[(size_t)row0 * P + col] = c[mi][ni][0];
                    outb[(size_t)(row0 + 8) * P + col] = c[mi][ni][2];
                }
            }
        }
    }
}

// ---------------- windowed attention: tf32 mma, shfl P-transpose ------------
// block = (bn, head), 128 threads = 4 warps. Warp w owns q rows [16w, 16w+16).
// qs: [qpos][ch] stride 36 (A-frag reads conflict-free).
// ks/vs: [ch][pos] stride 68 (staging STS + PV B-frag reads conflict-free;
//        S-phase B reads 2-way).
// P C-frag -> A-frag via shfl (no smem tile).
__global__ __launch_bounds__(128)
void attn_mma_kernel() {
    __shared__ uint32_t qs[64][36];
    __shared__ uint32_t ks[32][68];
    __shared__ uint32_t vs[32][68];

    int bn = blockIdx.x;
    int h  = blockIdx.y;
    int b = bn / NWIN, n = bn % NWIN;
    int wh = n / 10, ww = n % 10;
    int tid = threadIdx.x, lane = tid & 31, warp = tid >> 5;
    int g = lane >> 2, tq = lane & 3;

    int y0q = 6 * wh, x0q = 6 * ww;
    int y0k = 24 * wh, x0k = 24 * ww;
    const float scale = 0.17677669529663687f; // 1/sqrt(32)

    // stage q (64 pos x 32 ch), fold scale
    for (int e = tid; e < 2048; e += 128) {
        int c = e >> 6, i = e & 63;
        int dy = i >> 3, dx = i & 7;
        qs[i][c] = f2tf32(
            g_q[((size_t)(b * DIM + h * 32 + c) * HS + y0q + dy) * HS + x0q + dx] * scale);
    }

    float oacc[4][4];
#pragma unroll
    for (int ni = 0; ni < 4; ni++)
#pragma unroll
        for (int r = 0; r < 4; r++) oacc[ni][r] = 0.0f;
    float mrow0 = -1e30f, mrow1 = -1e30f, lrow0 = 0.0f, lrow1 = 0.0f;

    int m0 = warp * 16;
    int srcl  = (lane & 28) + (tq >> 1);
    int srcl2 = srcl + 2;
    bool odd = (tq & 1);
    __syncthreads();

    for (int c0 = 0; c0 < 1024; c0 += 64) {
        // stage K/V chunk: [ch][pos], coalesced gmem, conflict-free STS
        for (int e = tid; e < 2048; e += 128) {
            int ch = e >> 6, j = e & 63;
            int kj = c0 + j;
            int ky = y0k + (kj >> 5), kx = x0k + (kj & 31);
            ks[ch][j] = f2tf32(g_kv[((size_t)(b * 2 * DIM + h * 32 + ch) * HX + ky) * HX + kx]);
            vs[ch][j] = f2tf32(g_kv[((size_t)(b * 2 * DIM + DIM + h * 32 + ch) * HX + ky) * HX + kx]);
        }
        __syncthreads();

        // ---- S = Q K^T (16 x 64 per warp) ----
        float sc[8][4];
#pragma unroll
        for (int ni = 0; ni < 8; ni++)
#pragma unroll
            for (int r = 0; r < 4; r++) sc[ni][r] = 0.0f;

#pragma unroll
        for (int k0 = 0; k0 < 4; k0++) {
            uint32_t a0 = qs[m0 + g][k0 * 8 + tq];
            uint32_t a1 = qs[m0 + g + 8][k0 * 8 + tq];
            uint32_t a2 = qs[m0 + g][k0 * 8 + tq + 4];
            uint32_t a3 = qs[m0 + g + 8][k0 * 8 + tq + 4];
#pragma unroll
            for (int ni = 0; ni < 8; ni++) {
                uint32_t b0 = ks[k0 * 8 + tq][ni * 8 + g];
                uint32_t b1 = ks[k0 * 8 + tq + 4][ni * 8 + g];
                MMA_TF32(sc[ni][0], sc[ni][1], sc[ni][2], sc[ni][3],
                         a0, a1, a2, a3, b0, b1);
            }
        }

        // ---- streaming softmax on fragments ----
        float mx0 = -1e30f, mx1 = -1e30f;
#pragma unroll
        for (int ni = 0; ni < 8; ni++) {
            mx0 = fmaxf(mx0, fmaxf(sc[ni][0], sc[ni][1]));
            mx1 = fmaxf(mx1, fmaxf(sc[ni][2], sc[ni][3]));
        }
#pragma unroll
        for (int off = 1; off <= 2; off <<= 1) {
            mx0 = fmaxf(mx0, __shfl_xor_sync(0xFFFFFFFFu, mx0, off));
            mx1 = fmaxf(mx1, __shfl_xor_sync(0xFFFFFFFFu, mx1, off));
        }
        float mn0 = fmaxf(mrow0, mx0), mn1 = fmaxf(mrow1, mx1);
        float cor0 = __expf(mrow0 - mn0), cor1 = __expf(mrow1 - mn1);
        mrow0 = mn0; mrow1 = mn1;

        float s0 = 0.0f, s1 = 0.0f;
#pragma unroll
        for (int ni = 0; ni < 8; ni++) {
            sc[ni][0] = __expf(sc[ni][0] - mn0);
            sc[ni][1] = __expf(sc[ni][1] - mn0);
            sc[ni][2] = __expf(sc[ni][2] - mn1);
            sc[ni][3] = __expf(sc[ni][3] - mn1);
            s0 += sc[ni][0] + sc[ni][1];
            s1 += sc[ni][2] + sc[ni][3];
        }
#pragma unroll
        for (int off = 1; off <= 2; off <<= 1) {
            s0 += __shfl_xor_sync(0xFFFFFFFFu, s0, off);
            s1 += __shfl_xor_sync(0xFFFFFFFFu, s1, off);
        }
        lrow0 = lrow0 * cor0 + s0;
        lrow1 = lrow1 * cor1 + s1;
#pragma unroll
        for (int ni = 0; ni < 4; ni++) {
            oacc[ni][0] *= cor0; oacc[ni][1] *= cor0;
            oacc[ni][2] *= cor1; oacc[ni][3] *= cor1;
        }

        // ---- O += P V : A-frags from P via shfl transpose ----
#pragma unroll
        for (int kk = 0; kk < 8; kk++) {
            uint32_t p0 = f2tf32(sc[kk][0]);
            uint32_t p1 = f2tf32(sc[kk][1]);
            uint32_t p2 = f2tf32(sc[kk][2]);
            uint32_t p3 = f2tf32(sc[kk][3]);
            uint32_t q00 = __shfl_sync(0xFFFFFFFFu, p0, srcl);
            uint32_t q10 = __shfl_sync(0xFFFFFFFFu, p1, srcl);
            uint32_t q20 = __shfl_sync(0xFFFFFFFFu, p2, srcl);
            uint32_t q30 = __shfl_sync(0xFFFFFFFFu, p3, srcl);
            uint32_t q01 = __shfl_sync(0xFFFFFFFFu, p0, srcl2);
            uint32_t q11 = __shfl_sync(0xFFFFFFFFu, p1, srcl2);
            uint32_t q21 = __shfl_sync(0xFFFFFFFFu, p2, srcl2);
            uint32_t q31 = __shfl_sync(0xFFFFFFFFu, p3, srcl2);
            uint32_t a0 = odd ? q10 : q00;   // P[g   ][kk*8+tq  ]
            uint32_t a1 = odd ? q30 : q20;   // P[g+8 ][kk*8+tq  ]
            uint32_t a2 = odd ? q11 : q01;   // P[g   ][kk*8+tq+4]
            uint32_t a3 = odd ? q31 : q21;   // P[g+8 ][kk*8+tq+4]
#pragma unroll
            for (int ni = 0; ni < 4; ni++) {
                uint32_t b0 = vs[ni * 8 + g][kk * 8 + tq];
                uint32_t b1 = vs[ni * 8 + g][kk * 8 + tq + 4];
                MMA_TF32(oacc[ni][0], oacc[ni][1], oacc[ni][2], oacc[ni][3],
                         a0, a1, a2, a3, b0, b1);
            }
        }
        __syncthreads();
    }

    float inv0 = 1.0f / lrow0, inv1 = 1.0f / lrow1;
#pragma unroll
    for (int ni = 0; ni < 4; ni++) {
        int col = h * 32 + ni * 8 + 2 * tq;
        size_t base = (size_t)bn * DIM;
        g_win[(base + col) * 64 + m0 + g]         = oacc[ni][0] * inv0;
        g_win[(base + col + 1) * 64 + m0 + g]     = oacc[ni][1] * inv0;
        g_win[(base + col) * 64 + m0 + g + 8]     = oacc[ni][2] * inv1;
        g_win[(base + col + 1) * 64 + m0 + g + 8] = oacc[ni][3] * inv1;
    }
}

// ---------------- reverse (overlap-add with count normalization) ------------
__global__ void reverse_kernel() {
    int idx = blockIdx.x * 256 + threadIdx.x;
    if (idx >= BATCH * DIM * PS_S) return;
    int x = idx % HS;
    int y = (idx / HS) % HS;
    int c = (idx / PS_S) % DIM;
    int b = idx / (PS_S * DIM);

    int wlo = max(0, (y - 2) / 6), whi = min(9, y / 6);
    int vlo = max(0, (x - 2) / 6), vhi = min(9, x / 6);
    float s = 0.0f;
    for (int wh = wlo; wh <= whi; wh++) {
        int dy = y - 6 * wh;
        for (int ww = vlo; ww <= vhi; ww++) {
            int dx = x - 6 * ww;
            int n = wh * 10 + ww;
            s += g_win[((size_t)(b * NWIN + n) * DIM + c) * 64 + dy * 8 + dx];
        }
    }
    int cnt = (whi - wlo + 1) * (vhi - vlo + 1);
    g_acc[idx] = s / (float)cnt;
}

// ---------------- launch --------------------------------------------------
extern "C" void kernel_launch(void* const* d_in, const int* in_sizes, int n_in,
                              void* d_out, int out_size) {
    const float* x     = (const float*)d_in[0];
    const float* sp    = (const float*)d_in[1];
    const float* w_pos = (const float*)d_in[2];
    const float* b_pos = (const float*)d_in[3];
    const float* w_q   = (const float*)d_in[4];
    const float* w_qdw = (const float*)d_in[5];
    const float* w_kv  = (const float*)d_in[6];
    const float* w_kvdw= (const float*)d_in[7];
    const float* w_out = (const float*)d_in[8];
    float* out = (float*)d_out;

    float *xp, *spp, *tkv, *kv, *tq, *q, *acc, *wq_t, *wkv_t, *wout_t;
    cudaGetSymbolAddress((void**)&xp,    g_xp);
    cudaGetSymbolAddress((void**)&spp,   g_spp);
    cudaGetSymbolAddress((void**)&tkv,   g_tkv);
    cudaGetSymbolAddress((void**)&kv,    g_kv);
    cudaGetSymbolAddress((void**)&tq,    g_tq);
    cudaGetSymbolAddress((void**)&q,     g_q);
    cudaGetSymbolAddress((void**)&acc,   g_acc);
    cudaGetSymbolAddress((void**)&wq_t,  g_wq_t);
    cudaGetSymbolAddress((void**)&wkv_t, g_wkv_t);
    cudaGetSymbolAddress((void**)&wout_t,g_wout_t);

    transpose_kernel<<<(DIM*DIM + 255)/256, 256>>>(w_q,   wq_t,   DIM,   DIM);
    transpose_kernel<<<(2*DIM*DIM + 255)/256, 256>>>(w_kv, wkv_t, 2*DIM, DIM);
    transpose_kernel<<<(DIM*DIM + 255)/256, 256>>>(w_out, wout_t, DIM,   DIM);

    int nqx = ((HX + 3) / 4) * ((HX + 3) / 4);   // quad-tiles per 248^2 plane
    int nqs = ((HS + 3) / 4) * ((HS + 3) / 4);   // quad-tiles per 62^2 plane

    dw3q_kernel<true, true><<<dim3((nqx + 255)/256, BATCH*DIM), 256>>>(
        x, xp, w_pos, b_pos, HX, HX, DIM);
    dw3q_kernel<true, true><<<dim3((nqs + 255)/256, BATCH*DIM), 256>>>(
        sp, spp, w_pos, b_pos, HS, HS, DIM);

    conv1_gemm_tf32<<<dim3((PS_S + 127)/128, 1, BATCH), 256>>>(wq_t, spp, tq, DIM, PS_S);
    dw3q_kernel<false, false><<<dim3((nqs + 255)/256, BATCH*DIM), 256>>>(
        tq, q, w_qdw, nullptr, HS, HS, DIM);

    conv1_gemm_tf32<<<dim3((PS_X + 127)/128, 2, BATCH), 256>>>(wkv_t, xp, tkv, 2*DIM, PS_X);
    dw3q_kernel<false, false><<<dim3((nqx + 255)/256, BATCH*2*DIM), 256>>>(
        tkv, kv, w_kvdw, nullptr, HX, HX, 2*DIM);

    attn_mma_kernel<<<dim3(BATCH*NWIN, 4), 128>>>();

    reverse_kernel<<<(BATCH*DIM*PS_S + 255)/256, 256>>>();

    conv1_gemm_tf32<<<dim3((PS_S + 127)/128, 1, BATCH), 256>>>(wout_t, acc, out, DIM, PS_S);
}

// round 6
// speedup vs baseline: 3.0400x; 1.2057x over previous
#include <cuda_runtime.h>
#include <cstdint>

#define BATCH 2
#define DIM   128
#define HS    62
#define HX    248
#define PS_S  (HS*HS)   // 3844
#define PS_X  (HX*HX)   // 61504
#define NWIN  100       // 10x10 windows

// ---------------- scratch ----------------------------------------------------
__device__ float g_xp  [BATCH*DIM*PS_X];
__device__ float g_spp [BATCH*DIM*PS_S];
__device__ float g_tkv [BATCH*2*DIM*PS_X];
__device__ float g_kv  [BATCH*2*DIM*PS_X];   // tf32-rounded values
__device__ float g_tq  [BATCH*DIM*PS_S];
__device__ float g_q   [BATCH*DIM*PS_S];     // tf32-rounded, scale folded
__device__ float g_win [BATCH*NWIN*DIM*64];
__device__ float g_acc [BATCH*DIM*PS_S];
__device__ float g_wq_t  [DIM*DIM];
__device__ float g_wkv_t [DIM*2*DIM];
__device__ float g_wout_t[DIM*DIM];

__device__ __forceinline__ uint32_t f2tf32(float f) {
    uint32_t u;
    asm("cvt.rna.tf32.f32 %0, %1;" : "=r"(u) : "f"(f));
    return u;
}

#define MMA_TF32(C0,C1,C2,C3,A0,A1,A2,A3,B0,B1)                               \
    asm volatile(                                                             \
        "mma.sync.aligned.m16n8k8.row.col.f32.tf32.tf32.f32 "                 \
        "{%0,%1,%2,%3}, {%4,%5,%6,%7}, {%8,%9}, {%0,%1,%2,%3};"               \
        : "+f"(C0), "+f"(C1), "+f"(C2), "+f"(C3)                              \
        : "r"(A0), "r"(A1), "r"(A2), "r"(A3), "r"(B0), "r"(B1))

__device__ __forceinline__ void cp16(uint32_t dst, const void* src) {
    asm volatile("cp.async.cg.shared.global [%0], [%1], 16;" :: "r"(dst), "l"(src));
}

// ---------------- weight transpose (optional scale fold) ---------------------
__global__ void transpose_kernel(const float* __restrict__ w, float* __restrict__ wt,
                                 int O, int C, float smul) {
    int idx = blockIdx.x * 256 + threadIdx.x;
    if (idx >= O * C) return;
    int o = idx / C, c = idx % C;
    wt[c * O + o] = w[idx] * smul;
}

// ---------------- depthwise 3x3, 4x4 px/thread -------------------------------
// RES folded into center weight; VEC uses float4 middle loads (W mult of 4).
template<bool RES, bool BIAS, bool VEC, bool OTF32>
__global__ void dw3q_kernel(const float* __restrict__ in, float* __restrict__ out,
                            const float* __restrict__ w, const float* __restrict__ bias,
                            int H, int W, int cmod) {
    int plane = blockIdx.y;
    int nqx = (W + 3) >> 2, nqy = (H + 3) >> 2;
    int qidx = blockIdx.x * 256 + threadIdx.x;
    if (qidx >= nqx * nqy) return;
    int y0 = (qidx / nqx) << 2, x0 = (qidx % nqx) << 2;
    int c = plane % cmod;
    int HW = H * W;
    const float* ip = in + (size_t)plane * HW;
    const float* wc = w + c * 9;
    float w0[3] = {wc[0], wc[3], wc[6]};
    float w1[3] = {wc[1], wc[4] + (RES ? 1.0f : 0.0f), wc[7]};
    float w2[3] = {wc[2], wc[5], wc[8]};

    float acc[4][4];
    float binit = BIAS ? bias[c] : 0.0f;
#pragma unroll
    for (int r = 0; r < 4; r++)
#pragma unroll
        for (int j = 0; j < 4; j++) acc[r][j] = binit;

    bool xint = (x0 >= 4) && (x0 + 8 <= W);
    bool yint = (y0 >= 1) && (y0 + 5 <= H);

    if (VEC && xint && yint) {
#pragma unroll
        for (int iy = 0; iy < 6; iy++) {
            const float* rp = ip + (size_t)(y0 + iy - 1) * W;
            float4 mid = *(const float4*)(rp + x0);
            float v0 = rp[x0 - 1], v5 = rp[x0 + 4];
            float v[6] = {v0, mid.x, mid.y, mid.z, mid.w, v5};
#pragma unroll
            for (int r = 0; r < 4; r++) {
                int k = iy - r;
                if (k < 0 || k > 2) continue;
                float wy0 = w0[k], wy1 = w1[k], wy2 = w2[k];
#pragma unroll
                for (int j = 0; j < 4; j++)
                    acc[r][j] += v[j] * wy0 + v[j + 1] * wy1 + v[j + 2] * wy2;
            }
        }
    } else {
#pragma unroll
        for (int iy = 0; iy < 6; iy++) {
            int yy = y0 + iy - 1;
            if ((unsigned)yy >= (unsigned)H) continue;
            const float* rp = ip + (size_t)yy * W;
            float v[6];
#pragma unroll
            for (int i = 0; i < 6; i++) {
                int xx = x0 - 1 + i;
                v[i] = ((unsigned)xx < (unsigned)W) ? rp[xx] : 0.0f;
            }
#pragma unroll
            for (int r = 0; r < 4; r++) {
                int k = iy - r;
                if (k < 0 || k > 2) continue;
                float wy0 = w0[k], wy1 = w1[k], wy2 = w2[k];
#pragma unroll
                for (int j = 0; j < 4; j++)
                    acc[r][j] += v[j] * wy0 + v[j + 1] * wy1 + v[j + 2] * wy2;
            }
        }
    }
#pragma unroll
    for (int r = 0; r < 4; r++) {
        int yo = y0 + r;
        if (yo >= H) break;
        float* op = out + (size_t)plane * HW + (size_t)yo * W;
#pragma unroll
        for (int j = 0; j < 4; j++) {
            int xo = x0 + j;
            if (xo < W)
                op[xo] = OTF32 ? __uint_as_float(f2tf32(acc[r][j])) : acc[r][j];
        }
    }
}

// ---------------- conv1 as tf32 GEMM, double-buffered, 1 sync/chunk ----------
__global__ __launch_bounds__(256, 2)
void conv1_gemm_tf32(const float* __restrict__ Wt, const float* __restrict__ in,
                     float* __restrict__ out, int O, int P) {
    __shared__ uint32_t Ws[2][16][136];
    __shared__ uint32_t Xs[2][16][136];

    const float* inb = in + (size_t)blockIdx.z * 128 * P;
    float* outb = out + (size_t)blockIdx.z * O * P;

    int p0 = blockIdx.x * 128;
    int o0 = blockIdx.y * 128;
    int tid = threadIdx.x;
    int lane = tid & 31, warp = tid >> 5;
    int wo = warp >> 2;
    int wp = warp & 3;
    int g = lane >> 2;
    int tq = lane & 3;

    float c[4][4][4];
#pragma unroll
    for (int mi = 0; mi < 4; mi++)
#pragma unroll
        for (int ni = 0; ni < 4; ni++)
#pragma unroll
            for (int r = 0; r < 4; r++) c[mi][ni][r] = 0.0f;

    float wr[8], xr[8];
    // prologue: stage chunk 0
#pragma unroll
    for (int l = 0; l < 8; l++) {
        int e = tid + l * 256;
        int k = e >> 7, o = e & 127;
        wr[l] = Wt[(size_t)k * O + o0 + o];
        int gp = p0 + o;
        xr[l] = (gp < P) ? inb[(size_t)k * P + gp] : 0.0f;
    }
#pragma unroll
    for (int l = 0; l < 8; l++) {
        int e = tid + l * 256;
        int k = e >> 7, o = e & 127;
        Ws[0][k][o] = f2tf32(wr[l]);
        Xs[0][k][o] = f2tf32(xr[l]);
    }
    __syncthreads();

    for (int kc = 0; kc < 8; kc++) {
        int cur = kc & 1;
        if (kc < 7) {
            int kbase = (kc + 1) * 16;
#pragma unroll
            for (int l = 0; l < 8; l++) {
                int e = tid + l * 256;
                int k = e >> 7, o = e & 127;
                wr[l] = Wt[(size_t)(kbase + k) * O + o0 + o];
                int gp = p0 + o;
                xr[l] = (gp < P) ? inb[(size_t)(kbase + k) * P + gp] : 0.0f;
            }
        }
#pragma unroll
        for (int s = 0; s < 2; s++) {
            int kb = s * 8;
            uint32_t bf[4][2];
#pragma unroll
            for (int ni = 0; ni < 4; ni++) {
                int col = wp * 32 + ni * 8 + g;
                bf[ni][0] = Xs[cur][kb + tq][col];
                bf[ni][1] = Xs[cur][kb + tq + 4][col];
            }
            uint32_t af[4][4];
#pragma unroll
            for (int mi = 0; mi < 4; mi++) {
                int row = wo * 64 + mi * 16 + g;
                af[mi][0] = Ws[cur][kb + tq][row];
                af[mi][1] = Ws[cur][kb + tq][row + 8];
                af[mi][2] = Ws[cur][kb + tq + 4][row];
                af[mi][3] = Ws[cur][kb + tq + 4][row + 8];
            }
#pragma unroll
            for (int mi = 0; mi < 4; mi++)
#pragma unroll
                for (int ni = 0; ni < 4; ni++)
                    MMA_TF32(c[mi][ni][0], c[mi][ni][1], c[mi][ni][2], c[mi][ni][3],
                             af[mi][0], af[mi][1], af[mi][2], af[mi][3],
                             bf[ni][0], bf[ni][1]);
        }
        if (kc < 7) {
            int nb = cur ^ 1;
#pragma unroll
            for (int l = 0; l < 8; l++) {
                int e = tid + l * 256;
                int k = e >> 7, o = e & 127;
                Ws[nb][k][o] = f2tf32(wr[l]);
                Xs[nb][k][o] = f2tf32(xr[l]);
            }
        }
        __syncthreads();
    }

#pragma unroll
    for (int mi = 0; mi < 4; mi++) {
        int row0 = o0 + wo * 64 + mi * 16 + g;
#pragma unroll
        for (int ni = 0; ni < 4; ni++) {
            int col = p0 + wp * 32 + ni * 8 + 2 * tq;
            if (col + 1 < P) {
                float* r0 = outb + (size_t)row0 * P + col;
                float* r1 = outb + (size_t)(row0 + 8) * P + col;
                r0[0] = c[mi][ni][0]; r0[1] = c[mi][ni][1];
                r1[0] = c[mi][ni][2]; r1[1] = c[mi][ni][3];
            } else {
                if (col < P) {
                    outb[(size_t)row0 * P + col] = c[mi][ni][0];
                    outb[(size_t)(row0 + 8) * P + col] = c[mi][ni][2];
                }
            }
        }
    }
}

// ---------------- windowed attention: cp.async double-buffered K/V -----------
// g_q / g_kv already tf32-rounded (scale folded into w_q).
__global__ __launch_bounds__(128)
void attn_mma_kernel() {
    __shared__ uint32_t qs[64][36];
    __shared__ uint32_t ks[2][32][68];
    __shared__ uint32_t vs[2][32][68];

    int bn = blockIdx.x;
    int h  = blockIdx.y;
    int b = bn / NWIN, n = bn % NWIN;
    int wh = n / 10, ww = n % 10;
    int tid = threadIdx.x, lane = tid & 31, warp = tid >> 5;
    int g = lane >> 2, tq = lane & 3;

    int y0q = 6 * wh, x0q = 6 * ww;
    int y0k = 24 * wh, x0k = 24 * ww;

    uint32_t ks_base = (uint32_t)__cvta_generic_to_shared(&ks[0][0][0]);
    uint32_t vs_base = (uint32_t)__cvta_generic_to_shared(&vs[0][0][0]);

    // per-thread cp.async descriptors (8 x 16B per chunk)
    int u_ch[8], u_j[8], u_isv[8];
    const float* srcp[8];
#pragma unroll
    for (int t = 0; t < 8; t++) {
        int u = tid + (t << 7);
        int isv = u >> 9;
        int uu = u & 511;
        int ch = uu >> 4;
        int rem = uu & 15;
        int row = rem >> 3, kx = (rem & 7) << 2;
        u_ch[t] = ch; u_j[t] = (row << 5) + kx; u_isv[t] = isv;
        srcp[t] = g_kv + (((size_t)(b * 2 * DIM + isv * DIM + h * 32 + ch)) * HX
                          + (y0k + row)) * HX + x0k + kx;
    }

    // issue chunk 0 into buf 0
#pragma unroll
    for (int t = 0; t < 8; t++) {
        uint32_t dst = (u_isv[t] ? vs_base : ks_base) + (u_ch[t] * 68 + u_j[t]) * 4;
        cp16(dst, srcp[t]);
    }
    asm volatile("cp.async.commit_group;" ::: "memory");

    // stage q (bits already tf32, scale folded)
    const uint32_t* qsrc = (const uint32_t*)g_q;
    for (int e = tid; e < 2048; e += 128) {
        int c = e >> 6, i = e & 63;
        int dy = i >> 3, dx = i & 7;
        qs[i][c] = qsrc[((size_t)(b * DIM + h * 32 + c) * HS + y0q + dy) * HS + x0q + dx];
    }

    float oacc[4][4];
#pragma unroll
    for (int ni = 0; ni < 4; ni++)
#pragma unroll
        for (int r = 0; r < 4; r++) oacc[ni][r] = 0.0f;
    float mrow0 = -1e30f, mrow1 = -1e30f, lrow0 = 0.0f, lrow1 = 0.0f;

    int m0 = warp * 16;
    int srcl  = (lane & 28) + (tq >> 1);
    int srcl2 = srcl + 2;
    bool odd = (tq & 1);

    for (int i = 0; i < 16; i++) {
        int cur = i & 1;
        if (i < 15) {
            // issue chunk i+1 into other buffer (safe: sync at end of prev iter)
            int nb = cur ^ 1;
            int rowoff = (i + 1) * 2 * HX;
#pragma unroll
            for (int t = 0; t < 8; t++) {
                uint32_t dst = (u_isv[t] ? vs_base : ks_base)
                             + ((nb * 32 + u_ch[t]) * 68 + u_j[t]) * 4;
                cp16(dst, srcp[t] + rowoff);
            }
            asm volatile("cp.async.commit_group;" ::: "memory");
            asm volatile("cp.async.wait_group 1;" ::: "memory");
        } else {
            asm volatile("cp.async.wait_group 0;" ::: "memory");
        }
        __syncthreads();

        // ---- S = Q K^T (16 x 64 per warp) ----
        float sc[8][4];
#pragma unroll
        for (int ni = 0; ni < 8; ni++)
#pragma unroll
            for (int r = 0; r < 4; r++) sc[ni][r] = 0.0f;

#pragma unroll
        for (int k0 = 0; k0 < 4; k0++) {
            uint32_t a0 = qs[m0 + g][k0 * 8 + tq];
            uint32_t a1 = qs[m0 + g + 8][k0 * 8 + tq];
            uint32_t a2 = qs[m0 + g][k0 * 8 + tq + 4];
            uint32_t a3 = qs[m0 + g + 8][k0 * 8 + tq + 4];
#pragma unroll
            for (int ni = 0; ni < 8; ni++) {
                uint32_t b0 = ks[cur][k0 * 8 + tq][ni * 8 + g];
                uint32_t b1 = ks[cur][k0 * 8 + tq + 4][ni * 8 + g];
                MMA_TF32(sc[ni][0], sc[ni][1], sc[ni][2], sc[ni][3],
                         a0, a1, a2, a3, b0, b1);
            }
        }

        // ---- streaming softmax ----
        float mx0 = -1e30f, mx1 = -1e30f;
#pragma unroll
        for (int ni = 0; ni < 8; ni++) {
            mx0 = fmaxf(mx0, fmaxf(sc[ni][0], sc[ni][1]));
            mx1 = fmaxf(mx1, fmaxf(sc[ni][2], sc[ni][3]));
        }
#pragma unroll
        for (int off = 1; off <= 2; off <<= 1) {
            mx0 = fmaxf(mx0, __shfl_xor_sync(0xFFFFFFFFu, mx0, off));
            mx1 = fmaxf(mx1, __shfl_xor_sync(0xFFFFFFFFu, mx1, off));
        }
        float mn0 = fmaxf(mrow0, mx0), mn1 = fmaxf(mrow1, mx1);
        float cor0 = __expf(mrow0 - mn0), cor1 = __expf(mrow1 - mn1);
        mrow0 = mn0; mrow1 = mn1;

        float s0 = 0.0f, s1 = 0.0f;
#pragma unroll
        for (int ni = 0; ni < 8; ni++) {
            sc[ni][0] = __expf(sc[ni][0] - mn0);
            sc[ni][1] = __expf(sc[ni][1] - mn0);
            sc[ni][2] = __expf(sc[ni][2] - mn1);
            sc[ni][3] = __expf(sc[ni][3] - mn1);
            s0 += sc[ni][0] + sc[ni][1];
            s1 += sc[ni][2] + sc[ni][3];
        }
#pragma unroll
        for (int off = 1; off <= 2; off <<= 1) {
            s0 += __shfl_xor_sync(0xFFFFFFFFu, s0, off);
            s1 += __shfl_xor_sync(0xFFFFFFFFu, s1, off);
        }
        lrow0 = lrow0 * cor0 + s0;
        lrow1 = lrow1 * cor1 + s1;
#pragma unroll
        for (int ni = 0; ni < 4; ni++) {
            oacc[ni][0] *= cor0; oacc[ni][1] *= cor0;
            oacc[ni][2] *= cor1; oacc[ni][3] *= cor1;
        }

        // ---- O += P V : A-frags from P via shfl transpose ----
#pragma unroll
        for (int kk = 0; kk < 8; kk++) {
            uint32_t p0 = f2tf32(sc[kk][0]);
            uint32_t p1 = f2tf32(sc[kk][1]);
            uint32_t p2 = f2tf32(sc[kk][2]);
            uint32_t p3 = f2tf32(sc[kk][3]);
            uint32_t q00 = __shfl_sync(0xFFFFFFFFu, p0, srcl);
            uint32_t q10 = __shfl_sync(0xFFFFFFFFu, p1, srcl);
            uint32_t q20 = __shfl_sync(0xFFFFFFFFu, p2, srcl);
            uint32_t q30 = __shfl_sync(0xFFFFFFFFu, p3, srcl);
            uint32_t q01 = __shfl_sync(0xFFFFFFFFu, p0, srcl2);
            uint32_t q11 = __shfl_sync(0xFFFFFFFFu, p1, srcl2);
            uint32_t q21 = __shfl_sync(0xFFFFFFFFu, p2, srcl2);
            uint32_t q31 = __shfl_sync(0xFFFFFFFFu, p3, srcl2);
            uint32_t a0 = odd ? q10 : q00;
            uint32_t a1 = odd ? q30 : q20;
            uint32_t a2 = odd ? q11 : q01;
            uint32_t a3 = odd ? q31 : q21;
#pragma unroll
            for (int ni = 0; ni < 4; ni++) {
                uint32_t b0 = vs[cur][ni * 8 + g][kk * 8 + tq];
                uint32_t b1 = vs[cur][ni * 8 + g][kk * 8 + tq + 4];
                MMA_TF32(oacc[ni][0], oacc[ni][1], oacc[ni][2], oacc[ni][3],
                         a0, a1, a2, a3, b0, b1);
            }
        }
        __syncthreads();
    }

    float inv0 = 1.0f / lrow0, inv1 = 1.0f / lrow1;
#pragma unroll
    for (int ni = 0; ni < 4; ni++) {
        int col = h * 32 + ni * 8 + 2 * tq;
        size_t base = (size_t)bn * DIM;
        g_win[(base + col) * 64 + m0 + g]         = oacc[ni][0] * inv0;
        g_win[(base + col + 1) * 64 + m0 + g]     = oacc[ni][1] * inv0;
        g_win[(base + col) * 64 + m0 + g + 8]     = oacc[ni][2] * inv1;
        g_win[(base + col + 1) * 64 + m0 + g + 8] = oacc[ni][3] * inv1;
    }
}

// ---------------- reverse (overlap-add with count normalization) -------------
__global__ void reverse_kernel() {
    int idx = blockIdx.x * 256 + threadIdx.x;
    if (idx >= BATCH * DIM * PS_S) return;
    int x = idx % HS;
    int y = (idx / HS) % HS;
    int c = (idx / PS_S) % DIM;
    int b = idx / (PS_S * DIM);

    int wlo = max(0, (y - 2) / 6), whi = min(9, y / 6);
    int vlo = max(0, (x - 2) / 6), vhi = min(9, x / 6);
    float s = 0.0f;
    for (int wh = wlo; wh <= whi; wh++) {
        int dy = y - 6 * wh;
        for (int ww = vlo; ww <= vhi; ww++) {
            int dx = x - 6 * ww;
            int n = wh * 10 + ww;
            s += g_win[((size_t)(b * NWIN + n) * DIM + c) * 64 + dy * 8 + dx];
        }
    }
    int cnt = (whi - wlo + 1) * (vhi - vlo + 1);
    g_acc[idx] = s / (float)cnt;
}

// ---------------- launch -----------------------------------------------------
extern "C" void kernel_launch(void* const* d_in, const int* in_sizes, int n_in,
                              void* d_out, int out_size) {
    const float* x     = (const float*)d_in[0];
    const float* sp    = (const float*)d_in[1];
    const float* w_pos = (const float*)d_in[2];
    const float* b_pos = (const float*)d_in[3];
    const float* w_q   = (const float*)d_in[4];
    const float* w_qdw = (const float*)d_in[5];
    const float* w_kv  = (const float*)d_in[6];
    const float* w_kvdw= (const float*)d_in[7];
    const float* w_out = (const float*)d_in[8];
    float* out = (float*)d_out;

    float *xp, *spp, *tkv, *kv, *tq, *q, *acc, *wq_t, *wkv_t, *wout_t;
    cudaGetSymbolAddress((void**)&xp,    g_xp);
    cudaGetSymbolAddress((void**)&spp,   g_spp);
    cudaGetSymbolAddress((void**)&tkv,   g_tkv);
    cudaGetSymbolAddress((void**)&kv,    g_kv);
    cudaGetSymbolAddress((void**)&tq,    g_tq);
    cudaGetSymbolAddress((void**)&q,     g_q);
    cudaGetSymbolAddress((void**)&acc,   g_acc);
    cudaGetSymbolAddress((void**)&wq_t,  g_wq_t);
    cudaGetSymbolAddress((void**)&wkv_t, g_wkv_t);
    cudaGetSymbolAddress((void**)&wout_t,g_wout_t);

    const float scale = 0.17677669529663687f; // 1/sqrt(32), folded into w_q
    transpose_kernel<<<(DIM*DIM + 255)/256, 256>>>(w_q,   wq_t,   DIM,   DIM, scale);
    transpose_kernel<<<(2*DIM*DIM + 255)/256, 256>>>(w_kv, wkv_t, 2*DIM, DIM, 1.0f);
    transpose_kernel<<<(DIM*DIM + 255)/256, 256>>>(w_out, wout_t, DIM,   DIM, 1.0f);

    int nqx = ((HX + 3) / 4) * ((HX + 3) / 4);
    int nqs = ((HS + 3) / 4) * ((HS + 3) / 4);

    // pos convs (residual folded into center tap; bias)
    dw3q_kernel<true, true, true, false><<<dim3((nqx + 255)/256, BATCH*DIM), 256>>>(
        x, xp, w_pos, b_pos, HX, HX, DIM);
    dw3q_kernel<true, true, false, false><<<dim3((nqs + 255)/256, BATCH*DIM), 256>>>(
        sp, spp, w_pos, b_pos, HS, HS, DIM);

    // q path (output tf32-rounded for attention)
    conv1_gemm_tf32<<<dim3((PS_S + 127)/128, 1, BATCH), 256>>>(wq_t, spp, tq, DIM, PS_S);
    dw3q_kernel<false, false, false, true><<<dim3((nqs + 255)/256, BATCH*DIM), 256>>>(
        tq, q, w_qdw, nullptr, HS, HS, DIM);

    // kv path (output tf32-rounded for attention)
    conv1_gemm_tf32<<<dim3((PS_X + 127)/128, 2, BATCH), 256>>>(wkv_t, xp, tkv, 2*DIM, PS_X);
    dw3q_kernel<false, false, true, true><<<dim3((nqx + 255)/256, BATCH*2*DIM), 256>>>(
        tkv, kv, w_kvdw, nullptr, HX, HX, 2*DIM);

    attn_mma_kernel<<<dim3(BATCH*NWIN, 4), 128>>>();

    reverse_kernel<<<(BATCH*DIM*PS_S + 255)/256, 256>>>();

    conv1_gemm_tf32<<<dim3((PS_S + 127)/128, 1, BATCH), 256>>>(wout_t, acc, out, DIM, PS_S);
}